// round 9
// baseline (speedup 1.0000x reference)
#include <cuda_runtime.h>
#include <cstdint>

typedef unsigned int u32;

// LSTM B=65536, T=20, I=36, H=30. Gate order i,f,g,o.
// Output: out[B,T,H] ++ h_n[1,B,H] ++ c_n[1,B,H], fp32.
//
// mma.sync m16n8k16 bf16, 3-pass hi/lo compensation, M=32 per warp.
// N split into two halves (8+7 tiles): D[64] live, j-inner ILP preserved,
// A-frags rebuilt per half (transient 32 regs) -> ~170 regs -> 3 CTAs/SM.
// Half-0 h kept in regs until half-1 finishes reading h(t-1) from the slab.

#define NB   65536
#define NT   20
#define NIn  36
#define NH   30

#define BLOCK 128                 // 4 warps, 128 batches per CTA
#define GRID  (NB / 128)          // 512

#define PITCH 68                  // x 0..35 | h 36..65 | bias 66 | zero 67
#define SLAB_FLOATS (32 * PITCH)  // 2176
#define SLAB_BYTES  (SLAB_FLOATS * 4)   // 8704
#define NCHUNK 5                  // K = 80 (cols >= 67 have B = 0)
#define NTILE  15                 // N = 120 = 15 x 8, n = hh*4 + gate

#define B_ENTRIES (NCHUNK * NTILE * 32)       // 2400 uint4
#define OFF_SLAB  (B_ENTRIES * 16)            // 38400 bytes
#define SMEM_BYTES (OFF_SLAB + 4 * SLAB_BYTES + 256)  // 73472 (ch4 over-read pad)

__device__ __forceinline__ u32 bf16hi_u(float v) {
    return (__float_as_uint(v) + 0x8000u) & 0xFFFF0000u;
}
__device__ __forceinline__ u32 prmt_pack(u32 even_hi, u32 odd_hi) {
    u32 d;
    asm("prmt.b32 %0, %1, %2, 0x7632;" : "=r"(d) : "r"(even_hi), "r"(odd_hi));
    return d;
}
__device__ __forceinline__ u32 bf16x2_rn(float even, float odd) {
    u32 d;
    asm("cvt.rn.bf16x2.f32 %0, %1, %2;" : "=r"(d) : "f"(odd), "f"(even));
    return d;
}
__device__ __forceinline__ void mma_bf16(float* d, u32 a0, u32 a1, u32 a2, u32 a3,
                                         u32 b0, u32 b1) {
    asm volatile(
        "mma.sync.aligned.m16n8k16.row.col.f32.bf16.bf16.f32 "
        "{%0,%1,%2,%3}, {%4,%5,%6,%7}, {%8,%9}, {%0,%1,%2,%3};"
        : "+f"(d[0]), "+f"(d[1]), "+f"(d[2]), "+f"(d[3])
        : "r"(a0), "r"(a1), "r"(a2), "r"(a3), "r"(b0), "r"(b1));
}
__device__ __forceinline__ void mk_ahl(float2 f, u32& hi, u32& lo) {
    u32 he = bf16hi_u(f.x), ho = bf16hi_u(f.y);
    hi = prmt_pack(he, ho);
    lo = bf16x2_rn(f.x - __uint_as_float(he), f.y - __uint_as_float(ho));
}

__device__ __forceinline__ float sigmoid_f(float v) {
    return __fdividef(1.0f, 1.0f + __expf(-v));
}
__device__ __forceinline__ float tanh_f(float v) {
    return __fdividef(2.0f, 1.0f + __expf(-2.0f * v)) - 1.0f;
}

__device__ __forceinline__ u32 s2u(const void* p) {
    u32 a;
    asm("{ .reg .u64 t; cvta.to.shared.u64 t, %1; cvt.u32.u64 %0, t; }"
        : "=r"(a) : "l"(p));
    return a;
}
#define CP16(dst, src) \
    asm volatile("cp.async.ca.shared.global [%0], [%1], 16;" :: "r"(dst), "l"(src))
#define CP_COMMIT() asm volatile("cp.async.commit_group;" ::: "memory")
#define CP_WAIT0()  asm volatile("cp.async.wait_group 0;" ::: "memory")
#define COMPILER_MEMBAR() asm volatile("" ::: "memory")

// concatenated weight matrix: row n (gate-interleaved), col k in [0,80)
__device__ __forceinline__ float wcat(int n, int k,
                                      const float* W_ih, const float* W_hh,
                                      const float* b_ih, const float* b_hh) {
    int g = n & 3, hh = n >> 2;
    int row = g * NH + hh;
    if (k < 36) return W_ih[row * NIn + k];
    if (k < 66) return W_hh[row * NH + (k - 36)];
    if (k == 66) return b_ih[row] + b_hh[row];
    return 0.0f;
}

__global__ void __launch_bounds__(BLOCK, 3)
lstm_hmma_h2(const float* __restrict__ x,
             const float* __restrict__ W_ih,
             const float* __restrict__ W_hh,
             const float* __restrict__ b_ih,
             const float* __restrict__ b_hh,
             float* __restrict__ out) {
    extern __shared__ __align__(16) char smraw[];
    uint4* Bs   = reinterpret_cast<uint4*>(smraw);
    float* slab = reinterpret_cast<float*>(smraw + OFF_SLAB) + (threadIdx.x >> 5) * SLAB_FLOATS;

    const int tid  = threadIdx.x;
    const int lane = tid & 31;
    const int wB   = blockIdx.x * 128 + (tid >> 5) * 32;   // warp's first batch
    const u32 slab_u = s2u(slab);

    // ---- one-time B fragment prep (hi/lo bf16x2, per-lane layout) ----
    for (int idx = tid; idx < B_ENTRIES; idx += BLOCK) {
        int ch  = idx / (NTILE * 32);
        int rem = idx - ch * NTILE * 32;
        int j   = rem >> 5, ln = rem & 31;
        int n   = j * 8 + (ln >> 2);
        int kb  = 16 * ch + 2 * (ln & 3);
        float w00 = wcat(n, kb,     W_ih, W_hh, b_ih, b_hh);
        float w01 = wcat(n, kb + 1, W_ih, W_hh, b_ih, b_hh);
        float w10 = wcat(n, kb + 8, W_ih, W_hh, b_ih, b_hh);
        float w11 = wcat(n, kb + 9, W_ih, W_hh, b_ih, b_hh);
        u32 h00 = bf16hi_u(w00), h01 = bf16hi_u(w01);
        u32 h10 = bf16hi_u(w10), h11 = bf16hi_u(w11);
        uint4 e;
        e.x = prmt_pack(h00, h01);
        e.y = prmt_pack(h10, h11);
        e.z = bf16x2_rn(w00 - __uint_as_float(h00), w01 - __uint_as_float(h01));
        e.w = bf16x2_rn(w10 - __uint_as_float(h10), w11 - __uint_as_float(h11));
        Bs[idx] = e;
    }

    // ---- per-warp slab init: zeros, bias col 66 = 1 ----
#pragma unroll
    for (int i = lane; i < SLAB_FLOATS / 4; i += 32)
        *reinterpret_cast<float4*>(slab + 4 * i) = make_float4(0, 0, 0, 0);
    __syncwarp();
    slab[lane * PITCH + 66] = 1.0f;
    __syncthreads();

    // ---- prefetch x(t=0) via cp.async (cols 0..35 exactly) ----
#pragma unroll
    for (int k = 0; k < 9; k++) {
        int i = lane + 32 * k;          // 32 rows * 9 quads
        int rr = i / 9, q = i - rr * 9;
        CP16(slab_u + (rr * PITCH + 4 * q) * 4,
             x + (size_t)(wB + rr) * (NT * NIn) + 4 * q);
    }
    CP_COMMIT();

    const int r    = lane >> 2;               // frag row 0..7
    const bool ev  = (lane & 1) == 0;
    const int rowp = r + (ev ? 0 : 8);        // m0 cell row; m1 = rowp+16
    const int hsel = (lane >> 1) & 1;         // hh = 2j + hsel
    const int kofs = 2 * (lane & 3);

    float c0[NTILE], c1[NTILE];
#pragma unroll
    for (int j = 0; j < NTILE; j++) { c0[j] = 0.0f; c1[j] = 0.0f; }

    for (int t = 0; t < NT; t++) {
        CP_WAIT0();
        __syncwarp();                         // x(t) and h(t-1) visible

        float hreg[16];                       // half-0 new-h, deferred write

        // ================= HALF 0: tiles 0..7 =================
        {
            float D[64];
#pragma unroll
            for (int i = 0; i < 64; i++) D[i] = 0.0f;
#pragma unroll
            for (int ch = 0; ch < NCHUNK; ch++) {
                int kb = 16 * ch + kofs;
                u32 A[16];
                mk_ahl(*reinterpret_cast<const float2*>(slab + r * PITCH + kb),            A[0], A[4]);
                mk_ahl(*reinterpret_cast<const float2*>(slab + (r + 8) * PITCH + kb),      A[1], A[5]);
                mk_ahl(*reinterpret_cast<const float2*>(slab + r * PITCH + kb + 8),        A[2], A[6]);
                mk_ahl(*reinterpret_cast<const float2*>(slab + (r + 8) * PITCH + kb + 8),  A[3], A[7]);
                mk_ahl(*reinterpret_cast<const float2*>(slab + (r + 16) * PITCH + kb),     A[8], A[12]);
                mk_ahl(*reinterpret_cast<const float2*>(slab + (r + 24) * PITCH + kb),     A[9], A[13]);
                mk_ahl(*reinterpret_cast<const float2*>(slab + (r + 16) * PITCH + kb + 8), A[10], A[14]);
                mk_ahl(*reinterpret_cast<const float2*>(slab + (r + 24) * PITCH + kb + 8), A[11], A[15]);
#pragma unroll
                for (int j = 0; j < 8; j++) {
                    uint4 B = Bs[(ch * NTILE + j) * 32 + lane];
                    float* Dj = D + 8 * j;
                    mma_bf16(Dj,     A[0], A[1], A[2],  A[3],  B.x, B.y);
                    mma_bf16(Dj + 4, A[8], A[9], A[10], A[11], B.x, B.y);
                    mma_bf16(Dj,     A[4], A[5], A[6],  A[7],  B.x, B.y);
                    mma_bf16(Dj + 4, A[12],A[13],A[14], A[15], B.x, B.y);
                    mma_bf16(Dj,     A[0], A[1], A[2],  A[3],  B.z, B.w);
                    mma_bf16(Dj + 4, A[8], A[9], A[10], A[11], B.z, B.w);
                }
            }
#pragma unroll
            for (int j = 0; j < 8; j++) {
#pragma unroll
                for (int m = 0; m < 2; m++) {
                    float* Dm = D + 8 * j + 4 * m;
                    float d0 = Dm[0], d1 = Dm[1], d2 = Dm[2], d3 = Dm[3];
                    float e0 = __shfl_xor_sync(0xffffffffu, d0, 1);
                    float e1 = __shfl_xor_sync(0xffffffffu, d1, 1);
                    float e2 = __shfl_xor_sync(0xffffffffu, d2, 1);
                    float e3 = __shfl_xor_sync(0xffffffffu, d3, 1);
                    float gi = ev ? d0 : e2;
                    float gf = ev ? d1 : e3;
                    float gg = ev ? e0 : d2;
                    float go = ev ? e1 : d3;
                    float it = sigmoid_f(gi), ft = sigmoid_f(gf);
                    float gt = tanh_f(gg),    ot = sigmoid_f(go);
                    float* cr = m ? c1 : c0;
                    float cn = fmaf(ft, cr[j], it * gt);
                    cr[j] = cn;
                    hreg[2 * j + m] = ot * tanh_f(cn);   // DEFERRED slab write
                }
            }
        }
        COMPILER_MEMBAR();   // force half-1 to reload A from the slab

        // ================= HALF 1: tiles 8..14 =================
        {
            float D[56];
#pragma unroll
            for (int i = 0; i < 56; i++) D[i] = 0.0f;
#pragma unroll
            for (int ch = 0; ch < NCHUNK; ch++) {
                int kb = 16 * ch + kofs;
                u32 A[16];
                mk_ahl(*reinterpret_cast<const float2*>(slab + r * PITCH + kb),            A[0], A[4]);
                mk_ahl(*reinterpret_cast<const float2*>(slab + (r + 8) * PITCH + kb),      A[1], A[5]);
                mk_ahl(*reinterpret_cast<const float2*>(slab + r * PITCH + kb + 8),        A[2], A[6]);
                mk_ahl(*reinterpret_cast<const float2*>(slab + (r + 8) * PITCH + kb + 8),  A[3], A[7]);
                mk_ahl(*reinterpret_cast<const float2*>(slab + (r + 16) * PITCH + kb),     A[8], A[12]);
                mk_ahl(*reinterpret_cast<const float2*>(slab + (r + 24) * PITCH + kb),     A[9], A[13]);
                mk_ahl(*reinterpret_cast<const float2*>(slab + (r + 16) * PITCH + kb + 8), A[10], A[14]);
                mk_ahl(*reinterpret_cast<const float2*>(slab + (r + 24) * PITCH + kb + 8), A[11], A[15]);
#pragma unroll
                for (int j = 8; j < NTILE; j++) {
                    uint4 B = Bs[(ch * NTILE + j) * 32 + lane];
                    float* Dj = D + 8 * (j - 8);
                    mma_bf16(Dj,     A[0], A[1], A[2],  A[3],  B.x, B.y);
                    mma_bf16(Dj + 4, A[8], A[9], A[10], A[11], B.x, B.y);
                    mma_bf16(Dj,     A[4], A[5], A[6],  A[7],  B.x, B.y);
                    mma_bf16(Dj + 4, A[12],A[13],A[14], A[15], B.x, B.y);
                    mma_bf16(Dj,     A[0], A[1], A[2],  A[3],  B.z, B.w);
                    mma_bf16(Dj + 4, A[8], A[9], A[10], A[11], B.z, B.w);
                }
            }

            // slab x/h reads for this t all done -> prefetch x(t+1) now
            if (t < NT - 1) {
#pragma unroll
                for (int k = 0; k < 9; k++) {
                    int i = lane + 32 * k;
                    int rr = i / 9, q = i - rr * 9;
                    CP16(slab_u + (rr * PITCH + 4 * q) * 4,
                         x + (size_t)(wB + rr) * (NT * NIn) + (t + 1) * NIn + 4 * q);
                }
                CP_COMMIT();
            }

#pragma unroll
            for (int j = 8; j < NTILE; j++) {
#pragma unroll
                for (int m = 0; m < 2; m++) {
                    float* Dm = D + 8 * (j - 8) + 4 * m;
                    float d0 = Dm[0], d1 = Dm[1], d2 = Dm[2], d3 = Dm[3];
                    float e0 = __shfl_xor_sync(0xffffffffu, d0, 1);
                    float e1 = __shfl_xor_sync(0xffffffffu, d1, 1);
                    float e2 = __shfl_xor_sync(0xffffffffu, d2, 1);
                    float e3 = __shfl_xor_sync(0xffffffffu, d3, 1);
                    float gi = ev ? d0 : e2;
                    float gf = ev ? d1 : e3;
                    float gg = ev ? e0 : d2;
                    float go = ev ? e1 : d3;
                    float it = sigmoid_f(gi), ft = sigmoid_f(gf);
                    float gt = tanh_f(gg),    ot = sigmoid_f(go);
                    float* cr = m ? c1 : c0;
                    float cn = fmaf(ft, cr[j], it * gt);
                    cr[j] = cn;
                    slab[(rowp + 16 * m) * PITCH + 36 + (2 * j + hsel)] = ot * tanh_f(cn);
                }
            }
        }

        // flush half-0 h values to slab
#pragma unroll
        for (int j = 0; j < 8; j++) {
            slab[rowp * PITCH + 36 + (2 * j + hsel)]        = hreg[2 * j + 0];
            slab[(rowp + 16) * PITCH + 36 + (2 * j + hsel)] = hreg[2 * j + 1];
        }
        __syncwarp();

        // ---- out write: 32 rows x 30 from slab h cols ----
#pragma unroll
        for (int k = 0; k < 30; k++) {
            int i = lane + 32 * k;                  // < 960
            int rr = i / 30, cc = i - rr * 30;
            out[(size_t)(wB + rr) * (NT * NH) + t * NH + cc] =
                slab[rr * PITCH + 36 + cc];
        }
        __syncwarp();   // h reads done before next t's A-frag build
    }

    // ---- final states ----
    float* hN = out + (size_t)NB * NT * NH;
    float* cN = hN + (size_t)NB * NH;
#pragma unroll
    for (int k = 0; k < 30; k++) {
        int i = lane + 32 * k;
        int rr = i / 30, cc = i - rr * 30;
        hN[(size_t)(wB + rr) * NH + cc] = slab[rr * PITCH + 36 + cc];
    }
    __syncwarp();
#pragma unroll
    for (int j = 0; j < NTILE; j++) {
        slab[rowp * PITCH + 36 + (2 * j + hsel)]        = c0[j];
        slab[(rowp + 16) * PITCH + 36 + (2 * j + hsel)] = c1[j];
    }
    __syncwarp();
#pragma unroll
    for (int k = 0; k < 30; k++) {
        int i = lane + 32 * k;
        int rr = i / 30, cc = i - rr * 30;
        cN[(size_t)(wB + rr) * NH + cc] = slab[rr * PITCH + 36 + cc];
    }
}

extern "C" void kernel_launch(void* const* d_in, const int* in_sizes, int n_in,
                              void* d_out, int out_size) {
    const float* x    = (const float*)d_in[0];
    const float* W_ih = (const float*)d_in[1];
    const float* W_hh = (const float*)d_in[2];
    const float* b_ih = (const float*)d_in[3];
    const float* b_hh = (const float*)d_in[4];
    float* out = (float*)d_out;

    cudaFuncSetAttribute(lstm_hmma_h2,
                         cudaFuncAttributeMaxDynamicSharedMemorySize, SMEM_BYTES);
    lstm_hmma_h2<<<GRID, BLOCK, SMEM_BYTES>>>(x, W_ih, W_hh, b_ih, b_hh, out);
}

// round 10
// speedup vs baseline: 1.1561x; 1.1561x over previous
#include <cuda_runtime.h>
#include <cstdint>

typedef unsigned int u32;

// LSTM B=65536, T=20, I=36, H=30. Gate order i,f,g,o.
// Output: out[B,T,H] ++ h_n[1,B,H] ++ c_n[1,B,H], fp32.
//
// mma.sync bf16, 3-pass hi/lo compensation, M=32 per warp.
// A-fragments resident per timestep (72 regs, j-independent);
// D processed in 5 groups of 3 tiles (D[24] transient) -> ~166 regs
// -> 3 CTAs/SM with 71.9KB smem. Bias added in epilogue (K=66:
// 4 x k16 chunks + 1 x k8 chunk). PITCH=72: conflict-free A-build LDS.

#define NB   65536
#define NT   20
#define NIn  36
#define NH   30

#define BLOCK 128                 // 4 warps, 128 batches per CTA
#define GRID  (NB / 128)          // 512

#define PITCH 72                  // x 0..35 | h 36..65 | zeros 66..71
#define SLAB_FLOATS (32 * PITCH)  // 2304
#define SLAB_BYTES  (SLAB_FLOATS * 4)   // 9216
#define NTILE  15                 // N = 120 = 15 x 8, n = hh*4 + gate

// smem layout
#define OFF_B16  0                        // 4 ch * 15 j * 32 lanes * uint4 = 30720
#define OFF_B8   30720                    // 15 * 32 * uint2 = 3840
#define OFF_BIAS 34560                    // 30 * float4 = 480
#define OFF_SLAB 35040
#define SMEM_BYTES (OFF_SLAB + 4 * SLAB_BYTES)   // 71904

__device__ __forceinline__ u32 bf16hi_u(float v) {
    return (__float_as_uint(v) + 0x8000u) & 0xFFFF0000u;
}
__device__ __forceinline__ u32 prmt_pack(u32 even_hi, u32 odd_hi) {
    u32 d;
    asm("prmt.b32 %0, %1, %2, 0x7632;" : "=r"(d) : "r"(even_hi), "r"(odd_hi));
    return d;
}
__device__ __forceinline__ u32 bf16x2_rn(float even, float odd) {
    u32 d;
    asm("cvt.rn.bf16x2.f32 %0, %1, %2;" : "=r"(d) : "f"(odd), "f"(even));
    return d;
}
__device__ __forceinline__ void mma_k16(float* d, u32 a0, u32 a1, u32 a2, u32 a3,
                                        u32 b0, u32 b1) {
    asm volatile(
        "mma.sync.aligned.m16n8k16.row.col.f32.bf16.bf16.f32 "
        "{%0,%1,%2,%3}, {%4,%5,%6,%7}, {%8,%9}, {%0,%1,%2,%3};"
        : "+f"(d[0]), "+f"(d[1]), "+f"(d[2]), "+f"(d[3])
        : "r"(a0), "r"(a1), "r"(a2), "r"(a3), "r"(b0), "r"(b1));
}
__device__ __forceinline__ void mma_k8(float* d, u32 a0, u32 a1, u32 b0) {
    asm volatile(
        "mma.sync.aligned.m16n8k8.row.col.f32.bf16.bf16.f32 "
        "{%0,%1,%2,%3}, {%4,%5}, {%6}, {%0,%1,%2,%3};"
        : "+f"(d[0]), "+f"(d[1]), "+f"(d[2]), "+f"(d[3])
        : "r"(a0), "r"(a1), "r"(b0));
}
__device__ __forceinline__ void mk_ahl(float2 f, u32& hi, u32& lo) {
    u32 he = bf16hi_u(f.x), ho = bf16hi_u(f.y);
    hi = prmt_pack(he, ho);
    lo = bf16x2_rn(f.x - __uint_as_float(he), f.y - __uint_as_float(ho));
}

__device__ __forceinline__ float sigmoid_f(float v) {
    return __fdividef(1.0f, 1.0f + __expf(-v));
}
__device__ __forceinline__ float tanh_f(float v) {
    return __fdividef(2.0f, 1.0f + __expf(-2.0f * v)) - 1.0f;
}

__device__ __forceinline__ u32 s2u(const void* p) {
    u32 a;
    asm("{ .reg .u64 t; cvta.to.shared.u64 t, %1; cvt.u32.u64 %0, t; }"
        : "=r"(a) : "l"(p));
    return a;
}
#define CP16(dst, src) \
    asm volatile("cp.async.ca.shared.global [%0], [%1], 16;" :: "r"(dst), "l"(src))
#define CP_COMMIT() asm volatile("cp.async.commit_group;" ::: "memory")
#define CP_WAIT0()  asm volatile("cp.async.wait_group 0;" ::: "memory")

// concatenated weights, k in [0,66): x | h
__device__ __forceinline__ float wcat(int n, int k,
                                      const float* W_ih, const float* W_hh) {
    int g = n & 3, hh = n >> 2;
    int row = g * NH + hh;
    if (k < 36) return W_ih[row * NIn + k];
    if (k < 66) return W_hh[row * NH + (k - 36)];
    return 0.0f;
}

__global__ void __launch_bounds__(BLOCK, 3)
lstm_hmma_g3(const float* __restrict__ x,
             const float* __restrict__ W_ih,
             const float* __restrict__ W_hh,
             const float* __restrict__ b_ih,
             const float* __restrict__ b_hh,
             float* __restrict__ out) {
    extern __shared__ __align__(16) char smraw[];
    uint4*  Bs16 = reinterpret_cast<uint4*>(smraw + OFF_B16);
    uint2*  Bs8  = reinterpret_cast<uint2*>(smraw + OFF_B8);
    float4* Bias = reinterpret_cast<float4*>(smraw + OFF_BIAS);
    float*  slab = reinterpret_cast<float*>(smraw + OFF_SLAB) + (threadIdx.x >> 5) * SLAB_FLOATS;

    const int tid  = threadIdx.x;
    const int lane = tid & 31;
    const int wB   = blockIdx.x * 128 + (tid >> 5) * 32;   // warp's first batch
    const u32 slab_u = s2u(slab);

    // ---- one-time B16 fragment prep (4 k16 chunks, k = 0..63) ----
    for (int idx = tid; idx < 4 * NTILE * 32; idx += BLOCK) {
        int ch  = idx / (NTILE * 32);
        int rem = idx - ch * NTILE * 32;
        int j   = rem >> 5, ln = rem & 31;
        int n   = j * 8 + (ln >> 2);
        int kb  = 16 * ch + 2 * (ln & 3);
        float w00 = wcat(n, kb,     W_ih, W_hh);
        float w01 = wcat(n, kb + 1, W_ih, W_hh);
        float w10 = wcat(n, kb + 8, W_ih, W_hh);
        float w11 = wcat(n, kb + 9, W_ih, W_hh);
        u32 h00 = bf16hi_u(w00), h01 = bf16hi_u(w01);
        u32 h10 = bf16hi_u(w10), h11 = bf16hi_u(w11);
        uint4 e;
        e.x = prmt_pack(h00, h01);
        e.y = prmt_pack(h10, h11);
        e.z = bf16x2_rn(w00 - __uint_as_float(h00), w01 - __uint_as_float(h01));
        e.w = bf16x2_rn(w10 - __uint_as_float(h10), w11 - __uint_as_float(h11));
        Bs16[idx] = e;
    }
    // ---- B8 fragment prep (k8 chunk, k = 64..71; rows 64,65 real) ----
    for (int idx = tid; idx < NTILE * 32; idx += BLOCK) {
        int j = idx >> 5, ln = idx & 31;
        int n = j * 8 + (ln >> 2);
        int kl = 2 * (ln & 3);
        float w0 = (kl == 0) ? wcat(n, 64, W_ih, W_hh) : 0.0f;
        float w1 = (kl == 0) ? wcat(n, 65, W_ih, W_hh) : 0.0f;
        u32 h0 = bf16hi_u(w0), h1 = bf16hi_u(w1);
        uint2 e;
        e.x = prmt_pack(h0, h1);
        e.y = bf16x2_rn(w0 - __uint_as_float(h0), w1 - __uint_as_float(h1));
        Bs8[idx] = e;
    }
    // ---- bias table: Bias[hh] = (bi, bf, bg, bo) ----
    if (tid < NH) {
        Bias[tid] = make_float4(b_ih[0 * NH + tid] + b_hh[0 * NH + tid],
                                b_ih[1 * NH + tid] + b_hh[1 * NH + tid],
                                b_ih[2 * NH + tid] + b_hh[2 * NH + tid],
                                b_ih[3 * NH + tid] + b_hh[3 * NH + tid]);
    }

    // ---- per-warp slab init: all zeros (h=0, pad cols 66..71 = 0) ----
#pragma unroll
    for (int i = lane; i < SLAB_FLOATS / 4; i += 32)
        *reinterpret_cast<float4*>(slab + 4 * i) = make_float4(0, 0, 0, 0);
    __syncthreads();

    // ---- prefetch x(t=0) via cp.async (cols 0..35 exactly) ----
#pragma unroll
    for (int k = 0; k < 9; k++) {
        int i = lane + 32 * k;          // 32 rows * 9 quads
        int rr = i / 9, q = i - rr * 9;
        CP16(slab_u + (rr * PITCH + 4 * q) * 4,
             x + (size_t)(wB + rr) * (NT * NIn) + 4 * q);
    }
    CP_COMMIT();

    const int r    = lane >> 2;               // frag row 0..7
    const bool ev  = (lane & 1) == 0;
    const int rowp = r + (ev ? 0 : 8);        // m0 cell row; m1 = rowp+16
    const int hsel = (lane >> 1) & 1;         // hh = 2j + hsel
    const int kofs = 2 * (lane & 3);

    float c[NTILE * 2];                       // [j][m]
#pragma unroll
    for (int j = 0; j < NTILE * 2; j++) c[j] = 0.0f;

    for (int t = 0; t < NT; t++) {
        CP_WAIT0();
        __syncwarp();                         // x(t) and h(t-1) visible

        // ---- build ALL A fragments (resident: 64 + 8 regs) ----
        u32 A[4][16];
#pragma unroll
        for (int ch = 0; ch < 4; ch++) {
            int kb = 16 * ch + kofs;
            mk_ahl(*reinterpret_cast<const float2*>(slab + r * PITCH + kb),            A[ch][0], A[ch][4]);
            mk_ahl(*reinterpret_cast<const float2*>(slab + (r + 8) * PITCH + kb),      A[ch][1], A[ch][5]);
            mk_ahl(*reinterpret_cast<const float2*>(slab + r * PITCH + kb + 8),        A[ch][2], A[ch][6]);
            mk_ahl(*reinterpret_cast<const float2*>(slab + (r + 8) * PITCH + kb + 8),  A[ch][3], A[ch][7]);
            mk_ahl(*reinterpret_cast<const float2*>(slab + (r + 16) * PITCH + kb),     A[ch][8], A[ch][12]);
            mk_ahl(*reinterpret_cast<const float2*>(slab + (r + 24) * PITCH + kb),     A[ch][9], A[ch][13]);
            mk_ahl(*reinterpret_cast<const float2*>(slab + (r + 16) * PITCH + kb + 8), A[ch][10], A[ch][14]);
            mk_ahl(*reinterpret_cast<const float2*>(slab + (r + 24) * PITCH + kb + 8), A[ch][11], A[ch][15]);
        }
        u32 A8[8];   // k8 chunk, cols 64..71 (66..71 are zero)
        {
            int kb = 64 + kofs;
            mk_ahl(*reinterpret_cast<const float2*>(slab + r * PITCH + kb),        A8[0], A8[2]);
            mk_ahl(*reinterpret_cast<const float2*>(slab + (r + 8) * PITCH + kb),  A8[1], A8[3]);
            mk_ahl(*reinterpret_cast<const float2*>(slab + (r + 16) * PITCH + kb), A8[4], A8[6]);
            mk_ahl(*reinterpret_cast<const float2*>(slab + (r + 24) * PITCH + kb), A8[5], A8[7]);
        }

        // ---- all slab x-reads done: prefetch x(t+1) now ----
        if (t < NT - 1) {
#pragma unroll
            for (int k = 0; k < 9; k++) {
                int i = lane + 32 * k;
                int rr = i / 9, q = i - rr * 9;
                CP16(slab_u + (rr * PITCH + 4 * q) * 4,
                     x + (size_t)(wB + rr) * (NT * NIn) + (t + 1) * NIn + 4 * q);
            }
            CP_COMMIT();
        }

        // ---- 5 groups of 3 tiles: D[24] transient, epilogue per group ----
#pragma unroll
        for (int g = 0; g < 5; g++) {
            float D[24];
#pragma unroll
            for (int i = 0; i < 24; i++) D[i] = 0.0f;

#pragma unroll
            for (int ch = 0; ch < 4; ch++) {
#pragma unroll
                for (int jj = 0; jj < 3; jj++) {
                    int j = 3 * g + jj;
                    uint4 B = Bs16[(ch * NTILE + j) * 32 + lane];
                    float* Dj = D + 8 * jj;
                    mma_k16(Dj,     A[ch][0], A[ch][1], A[ch][2],  A[ch][3],  B.x, B.y);
                    mma_k16(Dj + 4, A[ch][8], A[ch][9], A[ch][10], A[ch][11], B.x, B.y);
                    mma_k16(Dj,     A[ch][4], A[ch][5], A[ch][6],  A[ch][7],  B.x, B.y);
                    mma_k16(Dj + 4, A[ch][12],A[ch][13],A[ch][14], A[ch][15], B.x, B.y);
                    mma_k16(Dj,     A[ch][0], A[ch][1], A[ch][2],  A[ch][3],  B.z, B.w);
                    mma_k16(Dj + 4, A[ch][8], A[ch][9], A[ch][10], A[ch][11], B.z, B.w);
                }
            }
#pragma unroll
            for (int jj = 0; jj < 3; jj++) {
                int j = 3 * g + jj;
                uint2 B8 = Bs8[j * 32 + lane];
                float* Dj = D + 8 * jj;
                mma_k8(Dj,     A8[0], A8[1], B8.x);
                mma_k8(Dj + 4, A8[4], A8[5], B8.x);
                mma_k8(Dj,     A8[2], A8[3], B8.x);
                mma_k8(Dj + 4, A8[6], A8[7], B8.x);
                mma_k8(Dj,     A8[0], A8[1], B8.y);
                mma_k8(Dj + 4, A8[4], A8[5], B8.y);
            }

            // epilogue: 3 tiles x 2 m; slab h write is safe (A in regs)
#pragma unroll
            for (int jj = 0; jj < 3; jj++) {
                int j = 3 * g + jj;
                float4 bb = Bias[2 * j + hsel];
#pragma unroll
                for (int m = 0; m < 2; m++) {
                    float* Dm = D + 8 * jj + 4 * m;
                    float d0 = Dm[0], d1 = Dm[1], d2 = Dm[2], d3 = Dm[3];
                    float e0 = __shfl_xor_sync(0xffffffffu, d0, 1);
                    float e1 = __shfl_xor_sync(0xffffffffu, d1, 1);
                    float e2 = __shfl_xor_sync(0xffffffffu, d2, 1);
                    float e3 = __shfl_xor_sync(0xffffffffu, d3, 1);
                    float gi = (ev ? d0 : e2) + bb.x;
                    float gf = (ev ? d1 : e3) + bb.y;
                    float gg = (ev ? e0 : d2) + bb.z;
                    float go = (ev ? e1 : d3) + bb.w;
                    float it = sigmoid_f(gi), ft = sigmoid_f(gf);
                    float gt = tanh_f(gg),    ot = sigmoid_f(go);
                    float cn = fmaf(ft, c[2 * j + m], it * gt);
                    c[2 * j + m] = cn;
                    slab[(rowp + 16 * m) * PITCH + 36 + (2 * j + hsel)] = ot * tanh_f(cn);
                }
            }
        }
        __syncwarp();

        // ---- out write: 32 rows x 30 from slab h cols ----
#pragma unroll
        for (int k = 0; k < 30; k++) {
            int i = lane + 32 * k;                  // < 960
            int rr = i / 30, cc = i - rr * 30;
            out[(size_t)(wB + rr) * (NT * NH) + t * NH + cc] =
                slab[rr * PITCH + 36 + cc];
        }
        __syncwarp();   // h reads done before next t's A-frag build
    }

    // ---- final states ----
    float* hN = out + (size_t)NB * NT * NH;
    float* cN = hN + (size_t)NB * NH;
#pragma unroll
    for (int k = 0; k < 30; k++) {
        int i = lane + 32 * k;
        int rr = i / 30, cc = i - rr * 30;
        hN[(size_t)(wB + rr) * NH + cc] = slab[rr * PITCH + 36 + cc];
    }
    __syncwarp();
#pragma unroll
    for (int j = 0; j < NTILE; j++) {
        slab[rowp * PITCH + 36 + (2 * j + hsel)]        = c[2 * j + 0];
        slab[(rowp + 16) * PITCH + 36 + (2 * j + hsel)] = c[2 * j + 1];
    }
    __syncwarp();
#pragma unroll
    for (int k = 0; k < 30; k++) {
        int i = lane + 32 * k;
        int rr = i / 30, cc = i - rr * 30;
        cN[(size_t)(wB + rr) * NH + cc] = slab[rr * PITCH + 36 + cc];
    }
}

extern "C" void kernel_launch(void* const* d_in, const int* in_sizes, int n_in,
                              void* d_out, int out_size) {
    const float* x    = (const float*)d_in[0];
    const float* W_ih = (const float*)d_in[1];
    const float* W_hh = (const float*)d_in[2];
    const float* b_ih = (const float*)d_in[3];
    const float* b_hh = (const float*)d_in[4];
    float* out = (float*)d_out;

    cudaFuncSetAttribute(lstm_hmma_g3,
                         cudaFuncAttributeMaxDynamicSharedMemorySize, SMEM_BYTES);
    lstm_hmma_g3<<<GRID, BLOCK, SMEM_BYTES>>>(x, W_ih, W_hh, b_ih, b_hh, out);
}

// round 11
// speedup vs baseline: 1.5755x; 1.3628x over previous
#include <cuda_runtime.h>
#include <cstdint>

typedef unsigned int u32;

// LSTM B=65536, T=20, I=36, H=30. Gate order i,f,g,o.
// Output: out[B,T,H] ++ h_n[1,B,H] ++ c_n[1,B,H], fp32.
//
// R7 skeleton (M=32/warp, D[120] live, ch-outer j-inner, 2 CTAs/SM) with:
//  - K = 72: x 0..35 | h 36..65 | bias col 66 (A=1) | zeros 67..71
//    -> 4 x k16 chunks + 1 x k8 chunk (no wasted 5th k16 chunk)
//  - x-chunks (k 0..31): fp16 2-pass (AhiBhi + AloBhi), B hi-only
//  - mixed/h chunks (k 32..63): bf16 3-pass ; k8 chunk: bf16 3-pass
//  - PITCH 72: bank-conflict-free A-build LDS.64 pattern

#define NB   65536
#define NT   20
#define NIn  36
#define NH   30

#define BLOCK 128                 // 4 warps, 128 batches per CTA
#define GRID  (NB / 128)          // 512

#define PITCH 72                  // x | h | bias(66)=1 | zeros
#define SLAB_FLOATS (32 * PITCH)  // 2304
#define SLAB_BYTES  (SLAB_FLOATS * 4)   // 9216
#define NTILE  15                 // N = 120 = 15 x 8, n = hh*4 + gate

// smem layout (bytes)
#define OFF_BF16 0                         // fp16 hi-only: 2ch*15j*32*uint2 = 7680
#define OFF_BB16 7680                      // bf16 hi/lo: 2ch*15j*32*uint4 = 15360
#define OFF_B8   23040                     // k8 bf16 hi/lo: 15j*32*uint2 = 3840
#define OFF_SLAB 26880
#define SMEM_BYTES (OFF_SLAB + 4 * SLAB_BYTES)   // 63744

// ---- bf16 helpers (established R6/R7 conventions: lower half = even elem) ----
__device__ __forceinline__ u32 bf16hi_u(float v) {
    return (__float_as_uint(v) + 0x8000u) & 0xFFFF0000u;
}
__device__ __forceinline__ u32 prmt_pack(u32 even_hi, u32 odd_hi) {
    u32 d;
    asm("prmt.b32 %0, %1, %2, 0x7632;" : "=r"(d) : "r"(even_hi), "r"(odd_hi));
    return d;
}
__device__ __forceinline__ u32 bf16x2_rn(float even, float odd) {
    u32 d;
    asm("cvt.rn.bf16x2.f32 %0, %1, %2;" : "=r"(d) : "f"(odd), "f"(even));
    return d;
}
__device__ __forceinline__ void mk_ahl(float2 f, u32& hi, u32& lo) {
    u32 he = bf16hi_u(f.x), ho = bf16hi_u(f.y);
    hi = prmt_pack(he, ho);
    lo = bf16x2_rn(f.x - __uint_as_float(he), f.y - __uint_as_float(ho));
}
// ---- fp16 helpers ----
__device__ __forceinline__ u32 f16x2_rn(float even, float odd) {
    u32 d;
    asm("cvt.rn.f16x2.f32 %0, %1, %2;" : "=r"(d) : "f"(odd), "f"(even));
    return d;
}
__device__ __forceinline__ void mk_ahl_f16(float2 f, u32& hi, u32& lo) {
    u32 h = f16x2_rn(f.x, f.y);
    float b0, b1;
    asm("{.reg .b16 l16, h16; mov.b32 {l16, h16}, %2;"
        " cvt.f32.f16 %0, l16; cvt.f32.f16 %1, h16;}"
        : "=f"(b0), "=f"(b1) : "r"(h));
    lo = f16x2_rn(f.x - b0, f.y - b1);
    hi = h;
}

// ---- MMA wrappers ----
__device__ __forceinline__ void mma_bf16(float* d, u32 a0, u32 a1, u32 a2, u32 a3,
                                         u32 b0, u32 b1) {
    asm volatile(
        "mma.sync.aligned.m16n8k16.row.col.f32.bf16.bf16.f32 "
        "{%0,%1,%2,%3}, {%4,%5,%6,%7}, {%8,%9}, {%0,%1,%2,%3};"
        : "+f"(d[0]), "+f"(d[1]), "+f"(d[2]), "+f"(d[3])
        : "r"(a0), "r"(a1), "r"(a2), "r"(a3), "r"(b0), "r"(b1));
}
__device__ __forceinline__ void mma_f16(float* d, u32 a0, u32 a1, u32 a2, u32 a3,
                                        u32 b0, u32 b1) {
    asm volatile(
        "mma.sync.aligned.m16n8k16.row.col.f32.f16.f16.f32 "
        "{%0,%1,%2,%3}, {%4,%5,%6,%7}, {%8,%9}, {%0,%1,%2,%3};"
        : "+f"(d[0]), "+f"(d[1]), "+f"(d[2]), "+f"(d[3])
        : "r"(a0), "r"(a1), "r"(a2), "r"(a3), "r"(b0), "r"(b1));
}
__device__ __forceinline__ void mma_k8(float* d, u32 a0, u32 a1, u32 b0) {
    asm volatile(
        "mma.sync.aligned.m16n8k8.row.col.f32.bf16.bf16.f32 "
        "{%0,%1,%2,%3}, {%4,%5}, {%6}, {%0,%1,%2,%3};"
        : "+f"(d[0]), "+f"(d[1]), "+f"(d[2]), "+f"(d[3])
        : "r"(a0), "r"(a1), "r"(b0));
}

__device__ __forceinline__ float sigmoid_f(float v) {
    return __fdividef(1.0f, 1.0f + __expf(-v));
}
__device__ __forceinline__ float tanh_f(float v) {
    return __fdividef(2.0f, 1.0f + __expf(-2.0f * v)) - 1.0f;
}

__device__ __forceinline__ u32 s2u(const void* p) {
    u32 a;
    asm("{ .reg .u64 t; cvta.to.shared.u64 t, %1; cvt.u32.u64 %0, t; }"
        : "=r"(a) : "l"(p));
    return a;
}
#define CP16(dst, src) \
    asm volatile("cp.async.cg.shared.global [%0], [%1], 16;" :: "r"(dst), "l"(src))
#define CP_COMMIT() asm volatile("cp.async.commit_group;" ::: "memory")
#define CP_WAIT0()  asm volatile("cp.async.wait_group 0;" ::: "memory")

// concatenated weights: row n (gate-interleaved), col k in [0,72)
__device__ __forceinline__ float wcat(int n, int k,
                                      const float* W_ih, const float* W_hh,
                                      const float* b_ih, const float* b_hh) {
    int g = n & 3, hh = n >> 2;
    int row = g * NH + hh;
    if (k < 36) return W_ih[row * NIn + k];
    if (k < 66) return W_hh[row * NH + (k - 36)];
    if (k == 66) return b_ih[row] + b_hh[row];
    return 0.0f;
}

__global__ void __launch_bounds__(BLOCK, 2)
lstm_hmma_k72(const float* __restrict__ x,
              const float* __restrict__ W_ih,
              const float* __restrict__ W_hh,
              const float* __restrict__ b_ih,
              const float* __restrict__ b_hh,
              float* __restrict__ out) {
    extern __shared__ __align__(16) char smraw[];
    uint2* BsF = reinterpret_cast<uint2*>(smraw + OFF_BF16);   // fp16 hi-only
    uint4* BsB = reinterpret_cast<uint4*>(smraw + OFF_BB16);   // bf16 hi/lo
    uint2* Bs8 = reinterpret_cast<uint2*>(smraw + OFF_B8);     // k8 bf16 hi/lo
    float* slab = reinterpret_cast<float*>(smraw + OFF_SLAB) + (threadIdx.x >> 5) * SLAB_FLOATS;

    const int tid  = threadIdx.x;
    const int lane = tid & 31;
    const int wB   = blockIdx.x * 128 + (tid >> 5) * 32;   // warp's first batch
    const u32 slab_u = s2u(slab);

    // ---- B tables (one-time) ----
    // fp16 hi-only chunks: k = 0..31 (pure x)
    for (int idx = tid; idx < 2 * NTILE * 32; idx += BLOCK) {
        int ch  = idx / (NTILE * 32);
        int rem = idx - ch * NTILE * 32;
        int j   = rem >> 5, ln = rem & 31;
        int n   = j * 8 + (ln >> 2);
        int kb  = 16 * ch + 2 * (ln & 3);
        uint2 e;
        e.x = f16x2_rn(wcat(n, kb,     W_ih, W_hh, b_ih, b_hh),
                       wcat(n, kb + 1, W_ih, W_hh, b_ih, b_hh));
        e.y = f16x2_rn(wcat(n, kb + 8, W_ih, W_hh, b_ih, b_hh),
                       wcat(n, kb + 9, W_ih, W_hh, b_ih, b_hh));
        BsF[idx] = e;
    }
    // bf16 hi/lo chunks: k = 32..63 (x tail + h)
    for (int idx = tid; idx < 2 * NTILE * 32; idx += BLOCK) {
        int ch  = idx / (NTILE * 32);
        int rem = idx - ch * NTILE * 32;
        int j   = rem >> 5, ln = rem & 31;
        int n   = j * 8 + (ln >> 2);
        int kb  = 32 + 16 * ch + 2 * (ln & 3);
        float w00 = wcat(n, kb,     W_ih, W_hh, b_ih, b_hh);
        float w01 = wcat(n, kb + 1, W_ih, W_hh, b_ih, b_hh);
        float w10 = wcat(n, kb + 8, W_ih, W_hh, b_ih, b_hh);
        float w11 = wcat(n, kb + 9, W_ih, W_hh, b_ih, b_hh);
        u32 h00 = bf16hi_u(w00), h01 = bf16hi_u(w01);
        u32 h10 = bf16hi_u(w10), h11 = bf16hi_u(w11);
        uint4 e;
        e.x = prmt_pack(h00, h01);
        e.y = prmt_pack(h10, h11);
        e.z = bf16x2_rn(w00 - __uint_as_float(h00), w01 - __uint_as_float(h01));
        e.w = bf16x2_rn(w10 - __uint_as_float(h10), w11 - __uint_as_float(h11));
        BsB[idx] = e;
    }
    // k8 chunk: k = 64..71 (h28, h29, bias, zeros)
    for (int idx = tid; idx < NTILE * 32; idx += BLOCK) {
        int j = idx >> 5, ln = idx & 31;
        int n = j * 8 + (ln >> 2);
        int kb = 64 + 2 * (ln & 3);
        float w0 = wcat(n, kb,     W_ih, W_hh, b_ih, b_hh);
        float w1 = wcat(n, kb + 1, W_ih, W_hh, b_ih, b_hh);
        u32 h0 = bf16hi_u(w0), h1 = bf16hi_u(w1);
        uint2 e;
        e.x = prmt_pack(h0, h1);
        e.y = bf16x2_rn(w0 - __uint_as_float(h0), w1 - __uint_as_float(h1));
        Bs8[idx] = e;
    }

    // ---- per-warp slab init: zeros, bias column 66 = 1 ----
#pragma unroll
    for (int i = lane; i < SLAB_FLOATS / 4; i += 32)
        *reinterpret_cast<float4*>(slab + 4 * i) = make_float4(0, 0, 0, 0);
    __syncwarp();
    slab[lane * PITCH + 66] = 1.0f;     // one row per lane
    __syncthreads();

    // ---- prefetch x(t=0) via cp.async (cols 0..35 exactly) ----
#pragma unroll
    for (int k = 0; k < 9; k++) {
        int i = lane + 32 * k;          // 32 rows * 9 quads
        int rr = i / 9, q = i - rr * 9;
        CP16(slab_u + (rr * PITCH + 4 * q) * 4,
             x + (size_t)(wB + rr) * (NT * NIn) + 4 * q);
    }
    CP_COMMIT();

    const int r    = lane >> 2;               // frag row 0..7
    const bool ev  = (lane & 1) == 0;
    const int rowp = r + (ev ? 0 : 8);        // m0 cell row; m1 = rowp+16
    const int hsel = (lane >> 1) & 1;         // hh = 2j + hsel
    const int kofs = 2 * (lane & 3);

    float c0[NTILE], c1[NTILE];
#pragma unroll
    for (int j = 0; j < NTILE; j++) { c0[j] = 0.0f; c1[j] = 0.0f; }

    for (int t = 0; t < NT; t++) {
        CP_WAIT0();
        __syncwarp();                         // x(t) and h(t-1) visible

        float D[8 * NTILE];                   // m0: 0..59, m1: 60..119
#pragma unroll
        for (int i = 0; i < 8 * NTILE; i++) D[i] = 0.0f;

        // ---- fp16 2-pass chunks: k 0..31 ----
#pragma unroll
        for (int ch = 0; ch < 2; ch++) {
            int kb = 16 * ch + kofs;
            u32 A[16];
            mk_ahl_f16(*reinterpret_cast<const float2*>(slab + r * PITCH + kb),            A[0], A[4]);
            mk_ahl_f16(*reinterpret_cast<const float2*>(slab + (r + 8) * PITCH + kb),      A[1], A[5]);
            mk_ahl_f16(*reinterpret_cast<const float2*>(slab + r * PITCH + kb + 8),        A[2], A[6]);
            mk_ahl_f16(*reinterpret_cast<const float2*>(slab + (r + 8) * PITCH + kb + 8),  A[3], A[7]);
            mk_ahl_f16(*reinterpret_cast<const float2*>(slab + (r + 16) * PITCH + kb),     A[8], A[12]);
            mk_ahl_f16(*reinterpret_cast<const float2*>(slab + (r + 24) * PITCH + kb),     A[9], A[13]);
            mk_ahl_f16(*reinterpret_cast<const float2*>(slab + (r + 16) * PITCH + kb + 8), A[10], A[14]);
            mk_ahl_f16(*reinterpret_cast<const float2*>(slab + (r + 24) * PITCH + kb + 8), A[11], A[15]);
#pragma unroll
            for (int j = 0; j < NTILE; j++) {
                uint2 B = BsF[(ch * NTILE + j) * 32 + lane];
                mma_f16(D + 4 * j,      A[0], A[1], A[2],  A[3],  B.x, B.y);  // m0 hi
                mma_f16(D + 60 + 4 * j, A[8], A[9], A[10], A[11], B.x, B.y);  // m1 hi
                mma_f16(D + 4 * j,      A[4], A[5], A[6],  A[7],  B.x, B.y);  // m0 lo
                mma_f16(D + 60 + 4 * j, A[12],A[13],A[14], A[15], B.x, B.y);  // m1 lo
            }
        }

        // ---- bf16 3-pass chunks: k 32..63 ----
#pragma unroll
        for (int ch = 0; ch < 2; ch++) {
            int kb = 32 + 16 * ch + kofs;
            u32 A[16];
            mk_ahl(*reinterpret_cast<const float2*>(slab + r * PITCH + kb),            A[0], A[4]);
            mk_ahl(*reinterpret_cast<const float2*>(slab + (r + 8) * PITCH + kb),      A[1], A[5]);
            mk_ahl(*reinterpret_cast<const float2*>(slab + r * PITCH + kb + 8),        A[2], A[6]);
            mk_ahl(*reinterpret_cast<const float2*>(slab + (r + 8) * PITCH + kb + 8),  A[3], A[7]);
            mk_ahl(*reinterpret_cast<const float2*>(slab + (r + 16) * PITCH + kb),     A[8], A[12]);
            mk_ahl(*reinterpret_cast<const float2*>(slab + (r + 24) * PITCH + kb),     A[9], A[13]);
            mk_ahl(*reinterpret_cast<const float2*>(slab + (r + 16) * PITCH + kb + 8), A[10], A[14]);
            mk_ahl(*reinterpret_cast<const float2*>(slab + (r + 24) * PITCH + kb + 8), A[11], A[15]);
#pragma unroll
            for (int j = 0; j < NTILE; j++) {
                uint4 B = BsB[(ch * NTILE + j) * 32 + lane];
                mma_bf16(D + 4 * j,      A[0], A[1], A[2],  A[3],  B.x, B.y);  // m0 hi*hi
                mma_bf16(D + 60 + 4 * j, A[8], A[9], A[10], A[11], B.x, B.y);  // m1 hi*hi
                mma_bf16(D + 4 * j,      A[4], A[5], A[6],  A[7],  B.x, B.y);  // m0 lo*hi
                mma_bf16(D + 60 + 4 * j, A[12],A[13],A[14], A[15], B.x, B.y);  // m1 lo*hi
                mma_bf16(D + 4 * j,      A[0], A[1], A[2],  A[3],  B.z, B.w);  // m0 hi*lo
                mma_bf16(D + 60 + 4 * j, A[8], A[9], A[10], A[11], B.z, B.w);  // m1 hi*lo
            }
        }

        // ---- k8 chunk: k 64..71 (h tail + bias) ----
        {
            int kb = 64 + kofs;
            u32 A8[8];
            mk_ahl(*reinterpret_cast<const float2*>(slab + r * PITCH + kb),        A8[0], A8[2]);
            mk_ahl(*reinterpret_cast<const float2*>(slab + (r + 8) * PITCH + kb),  A8[1], A8[3]);
            mk_ahl(*reinterpret_cast<const float2*>(slab + (r + 16) * PITCH + kb), A8[4], A8[6]);
            mk_ahl(*reinterpret_cast<const float2*>(slab + (r + 24) * PITCH + kb), A8[5], A8[7]);
#pragma unroll
            for (int j = 0; j < NTILE; j++) {
                uint2 B = Bs8[j * 32 + lane];
                mma_k8(D + 4 * j,      A8[0], A8[1], B.x);   // m0 hi*hi
                mma_k8(D + 60 + 4 * j, A8[4], A8[5], B.x);   // m1 hi*hi
                mma_k8(D + 4 * j,      A8[2], A8[3], B.x);   // m0 lo*hi
                mma_k8(D + 60 + 4 * j, A8[6], A8[7], B.x);   // m1 lo*hi
                mma_k8(D + 4 * j,      A8[0], A8[1], B.y);   // m0 hi*lo
                mma_k8(D + 60 + 4 * j, A8[4], A8[5], B.y);   // m1 hi*lo
            }
        }

        // ---- all slab reads done: prefetch x(t+1) ----
        if (t < NT - 1) {
#pragma unroll
            for (int k = 0; k < 9; k++) {
                int i = lane + 32 * k;
                int rr = i / 9, q = i - rr * 9;
                CP16(slab_u + (rr * PITCH + 4 * q) * 4,
                     x + (size_t)(wB + rr) * (NT * NIn) + (t + 1) * NIn + 4 * q);
            }
            CP_COMMIT();
        }

        // ---- epilogue: 2 cells per lane per ntile (m0, m1) ----
#pragma unroll
        for (int j = 0; j < NTILE; j++) {
#pragma unroll
            for (int m = 0; m < 2; m++) {
                float* Dm = D + 60 * m + 4 * j;
                float d0 = Dm[0], d1 = Dm[1], d2 = Dm[2], d3 = Dm[3];
                float e0 = __shfl_xor_sync(0xffffffffu, d0, 1);
                float e1 = __shfl_xor_sync(0xffffffffu, d1, 1);
                float e2 = __shfl_xor_sync(0xffffffffu, d2, 1);
                float e3 = __shfl_xor_sync(0xffffffffu, d3, 1);
                float gi = ev ? d0 : e2;
                float gf = ev ? d1 : e3;
                float gg = ev ? e0 : d2;
                float go = ev ? e1 : d3;
                float it = sigmoid_f(gi), ft = sigmoid_f(gf);
                float gt = tanh_f(gg),    ot = sigmoid_f(go);
                float* cr = m ? c1 : c0;
                float cn = fmaf(ft, cr[j], it * gt);
                cr[j] = cn;
                slab[(rowp + 16 * m) * PITCH + 36 + (2 * j + hsel)] = ot * tanh_f(cn);
            }
        }
        __syncwarp();

        // ---- out write: 32 rows x 30 from slab h cols ----
#pragma unroll
        for (int k = 0; k < 30; k++) {
            int i = lane + 32 * k;                  // < 960
            int rr = i / 30, cc = i - rr * 30;
            out[(size_t)(wB + rr) * (NT * NH) + t * NH + cc] =
                slab[rr * PITCH + 36 + cc];
        }
        __syncwarp();   // h reads done before next t's A-frag build
    }

    // ---- final states ----
    float* hN = out + (size_t)NB * NT * NH;
    float* cN = hN + (size_t)NB * NH;
#pragma unroll
    for (int k = 0; k < 30; k++) {
        int i = lane + 32 * k;
        int rr = i / 30, cc = i - rr * 30;
        hN[(size_t)(wB + rr) * NH + cc] = slab[rr * PITCH + 36 + cc];
    }
    __syncwarp();
#pragma unroll
    for (int j = 0; j < NTILE; j++) {
        slab[rowp * PITCH + 36 + (2 * j + hsel)]        = c0[j];
        slab[(rowp + 16) * PITCH + 36 + (2 * j + hsel)] = c1[j];
    }
    __syncwarp();
#pragma unroll
    for (int k = 0; k < 30; k++) {
        int i = lane + 32 * k;
        int rr = i / 30, cc = i - rr * 30;
        cN[(size_t)(wB + rr) * NH + cc] = slab[rr * PITCH + 36 + cc];
    }
}

extern "C" void kernel_launch(void* const* d_in, const int* in_sizes, int n_in,
                              void* d_out, int out_size) {
    const float* x    = (const float*)d_in[0];
    const float* W_ih = (const float*)d_in[1];
    const float* W_hh = (const float*)d_in[2];
    const float* b_ih = (const float*)d_in[3];
    const float* b_hh = (const float*)d_in[4];
    float* out = (float*)d_out;

    cudaFuncSetAttribute(lstm_hmma_k72,
                         cudaFuncAttributeMaxDynamicSharedMemorySize, SMEM_BYTES);
    lstm_hmma_k72<<<GRID, BLOCK, SMEM_BYTES>>>(x, W_ih, W_hh, b_ih, b_hh, out);
}

// round 12
// speedup vs baseline: 1.7370x; 1.1026x over previous
#include <cuda_runtime.h>
#include <cstdint>

typedef unsigned int u32;

// LSTM B=65536, T=20, I=36, H=30. Gate order i,f,g,o.
// Output: out[B,T,H] ++ h_n[1,B,H] ++ c_n[1,B,H], fp32.
//
// R11 skeleton (M=32/warp, D[120] live, ch-outer j-inner, 2 CTAs/SM) with:
//  - ALL k16 chunks (k 0..63, x+h) fp16 2-pass (AhiBhi + AloBhi), B hi-only
//  - k8 chunk (k 64..71: h tail + bias col 66) bf16 3-pass (bias lo-comp)
//  - epilogue shfl halved: selp+shfl serves both lane directions

#define NB   65536
#define NT   20
#define NIn  36
#define NH   30

#define BLOCK 128                 // 4 warps, 128 batches per CTA
#define GRID  (NB / 128)          // 512

#define PITCH 72                  // x 0..35 | h 36..65 | bias(66)=1 | zeros
#define SLAB_FLOATS (32 * PITCH)  // 2304
#define SLAB_BYTES  (SLAB_FLOATS * 4)   // 9216
#define NTILE  15                 // N = 120 = 15 x 8, n = hh*4 + gate

// smem layout (bytes)
#define OFF_BF16 0                         // fp16 hi-only: 4ch*15j*32*uint2 = 15360
#define OFF_B8   15360                     // k8 bf16 hi/lo: 15j*32*uint2 = 3840
#define OFF_SLAB 19200
#define SMEM_BYTES (OFF_SLAB + 4 * SLAB_BYTES)   // 56064

// ---- bf16 helpers ----
__device__ __forceinline__ u32 bf16hi_u(float v) {
    return (__float_as_uint(v) + 0x8000u) & 0xFFFF0000u;
}
__device__ __forceinline__ u32 prmt_pack(u32 even_hi, u32 odd_hi) {
    u32 d;
    asm("prmt.b32 %0, %1, %2, 0x7632;" : "=r"(d) : "r"(even_hi), "r"(odd_hi));
    return d;
}
__device__ __forceinline__ u32 bf16x2_rn(float even, float odd) {
    u32 d;
    asm("cvt.rn.bf16x2.f32 %0, %1, %2;" : "=r"(d) : "f"(odd), "f"(even));
    return d;
}
__device__ __forceinline__ void mk_ahl(float2 f, u32& hi, u32& lo) {
    u32 he = bf16hi_u(f.x), ho = bf16hi_u(f.y);
    hi = prmt_pack(he, ho);
    lo = bf16x2_rn(f.x - __uint_as_float(he), f.y - __uint_as_float(ho));
}
// ---- fp16 helpers ----
__device__ __forceinline__ u32 f16x2_rn(float even, float odd) {
    u32 d;
    asm("cvt.rn.f16x2.f32 %0, %1, %2;" : "=r"(d) : "f"(odd), "f"(even));
    return d;
}
__device__ __forceinline__ void mk_ahl_f16(float2 f, u32& hi, u32& lo) {
    u32 h = f16x2_rn(f.x, f.y);
    float b0, b1;
    asm("{.reg .b16 l16, h16; mov.b32 {l16, h16}, %2;"
        " cvt.f32.f16 %0, l16; cvt.f32.f16 %1, h16;}"
        : "=f"(b0), "=f"(b1) : "r"(h));
    lo = f16x2_rn(f.x - b0, f.y - b1);
    hi = h;
}

// ---- MMA wrappers ----
__device__ __forceinline__ void mma_f16(float* d, u32 a0, u32 a1, u32 a2, u32 a3,
                                        u32 b0, u32 b1) {
    asm volatile(
        "mma.sync.aligned.m16n8k16.row.col.f32.f16.f16.f32 "
        "{%0,%1,%2,%3}, {%4,%5,%6,%7}, {%8,%9}, {%0,%1,%2,%3};"
        : "+f"(d[0]), "+f"(d[1]), "+f"(d[2]), "+f"(d[3])
        : "r"(a0), "r"(a1), "r"(a2), "r"(a3), "r"(b0), "r"(b1));
}
__device__ __forceinline__ void mma_k8(float* d, u32 a0, u32 a1, u32 b0) {
    asm volatile(
        "mma.sync.aligned.m16n8k8.row.col.f32.bf16.bf16.f32 "
        "{%0,%1,%2,%3}, {%4,%5}, {%6}, {%0,%1,%2,%3};"
        : "+f"(d[0]), "+f"(d[1]), "+f"(d[2]), "+f"(d[3])
        : "r"(a0), "r"(a1), "r"(b0));
}

__device__ __forceinline__ float sigmoid_f(float v) {
    return __fdividef(1.0f, 1.0f + __expf(-v));
}
__device__ __forceinline__ float tanh_f(float v) {
    return __fdividef(2.0f, 1.0f + __expf(-2.0f * v)) - 1.0f;
}

__device__ __forceinline__ u32 s2u(const void* p) {
    u32 a;
    asm("{ .reg .u64 t; cvta.to.shared.u64 t, %1; cvt.u32.u64 %0, t; }"
        : "=r"(a) : "l"(p));
    return a;
}
#define CP16(dst, src) \
    asm volatile("cp.async.cg.shared.global [%0], [%1], 16;" :: "r"(dst), "l"(src))
#define CP_COMMIT() asm volatile("cp.async.commit_group;" ::: "memory")
#define CP_WAIT0()  asm volatile("cp.async.wait_group 0;" ::: "memory")

// concatenated weights: row n (gate-interleaved), col k in [0,72)
__device__ __forceinline__ float wcat(int n, int k,
                                      const float* W_ih, const float* W_hh,
                                      const float* b_ih, const float* b_hh) {
    int g = n & 3, hh = n >> 2;
    int row = g * NH + hh;
    if (k < 36) return W_ih[row * NIn + k];
    if (k < 66) return W_hh[row * NH + (k - 36)];
    if (k == 66) return b_ih[row] + b_hh[row];
    return 0.0f;
}

__global__ void __launch_bounds__(BLOCK, 2)
lstm_hmma_f16(const float* __restrict__ x,
              const float* __restrict__ W_ih,
              const float* __restrict__ W_hh,
              const float* __restrict__ b_ih,
              const float* __restrict__ b_hh,
              float* __restrict__ out) {
    extern __shared__ __align__(16) char smraw[];
    uint2* BsF = reinterpret_cast<uint2*>(smraw + OFF_BF16);   // fp16 hi-only
    uint2* Bs8 = reinterpret_cast<uint2*>(smraw + OFF_B8);     // k8 bf16 hi/lo
    float* slab = reinterpret_cast<float*>(smraw + OFF_SLAB) + (threadIdx.x >> 5) * SLAB_FLOATS;

    const int tid  = threadIdx.x;
    const int lane = tid & 31;
    const int wB   = blockIdx.x * 128 + (tid >> 5) * 32;   // warp's first batch
    const u32 slab_u = s2u(slab);

    // ---- B tables (one-time) ----
    // fp16 hi-only chunks: k = 0..63 (x and h; |w| <= 0.19, fp16-safe)
    for (int idx = tid; idx < 4 * NTILE * 32; idx += BLOCK) {
        int ch  = idx / (NTILE * 32);
        int rem = idx - ch * NTILE * 32;
        int j   = rem >> 5, ln = rem & 31;
        int n   = j * 8 + (ln >> 2);
        int kb  = 16 * ch + 2 * (ln & 3);
        uint2 e;
        e.x = f16x2_rn(wcat(n, kb,     W_ih, W_hh, b_ih, b_hh),
                       wcat(n, kb + 1, W_ih, W_hh, b_ih, b_hh));
        e.y = f16x2_rn(wcat(n, kb + 8, W_ih, W_hh, b_ih, b_hh),
                       wcat(n, kb + 9, W_ih, W_hh, b_ih, b_hh));
        BsF[idx] = e;
    }
    // k8 chunk: k = 64..71 (h28, h29, bias, zeros), bf16 hi/lo
    for (int idx = tid; idx < NTILE * 32; idx += BLOCK) {
        int j = idx >> 5, ln = idx & 31;
        int n = j * 8 + (ln >> 2);
        int kb = 64 + 2 * (ln & 3);
        float w0 = wcat(n, kb,     W_ih, W_hh, b_ih, b_hh);
        float w1 = wcat(n, kb + 1, W_ih, W_hh, b_ih, b_hh);
        u32 h0 = bf16hi_u(w0), h1 = bf16hi_u(w1);
        uint2 e;
        e.x = prmt_pack(h0, h1);
        e.y = bf16x2_rn(w0 - __uint_as_float(h0), w1 - __uint_as_float(h1));
        Bs8[idx] = e;
    }

    // ---- per-warp slab init: zeros, bias column 66 = 1 ----
#pragma unroll
    for (int i = lane; i < SLAB_FLOATS / 4; i += 32)
        *reinterpret_cast<float4*>(slab + 4 * i) = make_float4(0, 0, 0, 0);
    __syncwarp();
    slab[lane * PITCH + 66] = 1.0f;     // one row per lane
    __syncthreads();

    // ---- prefetch x(t=0) via cp.async (cols 0..35 exactly) ----
#pragma unroll
    for (int k = 0; k < 9; k++) {
        int i = lane + 32 * k;          // 32 rows * 9 quads
        int rr = i / 9, q = i - rr * 9;
        CP16(slab_u + (rr * PITCH + 4 * q) * 4,
             x + (size_t)(wB + rr) * (NT * NIn) + 4 * q);
    }
    CP_COMMIT();

    const int r    = lane >> 2;               // frag row 0..7
    const bool ev  = (lane & 1) == 0;
    const int rowp = r + (ev ? 0 : 8);        // m0 cell row; m1 = rowp+16
    const int hsel = (lane >> 1) & 1;         // hh = 2j + hsel
    const int kofs = 2 * (lane & 3);

    float c0[NTILE], c1[NTILE];
#pragma unroll
    for (int j = 0; j < NTILE; j++) { c0[j] = 0.0f; c1[j] = 0.0f; }

    for (int t = 0; t < NT; t++) {
        CP_WAIT0();
        __syncwarp();                         // x(t) and h(t-1) visible

        float D[8 * NTILE];                   // m0: 0..59, m1: 60..119
#pragma unroll
        for (int i = 0; i < 8 * NTILE; i++) D[i] = 0.0f;

        // ---- fp16 2-pass chunks: k 0..63 ----
#pragma unroll
        for (int ch = 0; ch < 4; ch++) {
            int kb = 16 * ch + kofs;
            u32 A[16];
            mk_ahl_f16(*reinterpret_cast<const float2*>(slab + r * PITCH + kb),            A[0], A[4]);
            mk_ahl_f16(*reinterpret_cast<const float2*>(slab + (r + 8) * PITCH + kb),      A[1], A[5]);
            mk_ahl_f16(*reinterpret_cast<const float2*>(slab + r * PITCH + kb + 8),        A[2], A[6]);
            mk_ahl_f16(*reinterpret_cast<const float2*>(slab + (r + 8) * PITCH + kb + 8),  A[3], A[7]);
            mk_ahl_f16(*reinterpret_cast<const float2*>(slab + (r + 16) * PITCH + kb),     A[8], A[12]);
            mk_ahl_f16(*reinterpret_cast<const float2*>(slab + (r + 24) * PITCH + kb),     A[9], A[13]);
            mk_ahl_f16(*reinterpret_cast<const float2*>(slab + (r + 16) * PITCH + kb + 8), A[10], A[14]);
            mk_ahl_f16(*reinterpret_cast<const float2*>(slab + (r + 24) * PITCH + kb + 8), A[11], A[15]);
#pragma unroll
            for (int j = 0; j < NTILE; j++) {
                uint2 B = BsF[(ch * NTILE + j) * 32 + lane];
                mma_f16(D + 4 * j,      A[0], A[1], A[2],  A[3],  B.x, B.y);  // m0 hi
                mma_f16(D + 60 + 4 * j, A[8], A[9], A[10], A[11], B.x, B.y);  // m1 hi
                mma_f16(D + 4 * j,      A[4], A[5], A[6],  A[7],  B.x, B.y);  // m0 lo
                mma_f16(D + 60 + 4 * j, A[12],A[13],A[14], A[15], B.x, B.y);  // m1 lo
            }
        }

        // ---- k8 chunk: k 64..71 (h tail + bias), bf16 3-pass ----
        {
            int kb = 64 + kofs;
            u32 A8[8];
            mk_ahl(*reinterpret_cast<const float2*>(slab + r * PITCH + kb),        A8[0], A8[2]);
            mk_ahl(*reinterpret_cast<const float2*>(slab + (r + 8) * PITCH + kb),  A8[1], A8[3]);
            mk_ahl(*reinterpret_cast<const float2*>(slab + (r + 16) * PITCH + kb), A8[4], A8[6]);
            mk_ahl(*reinterpret_cast<const float2*>(slab + (r + 24) * PITCH + kb), A8[5], A8[7]);
#pragma unroll
            for (int j = 0; j < NTILE; j++) {
                uint2 B = Bs8[j * 32 + lane];
                mma_k8(D + 4 * j,      A8[0], A8[1], B.x);   // m0 hi*hi
                mma_k8(D + 60 + 4 * j, A8[4], A8[5], B.x);   // m1 hi*hi
                mma_k8(D + 4 * j,      A8[2], A8[3], B.x);   // m0 lo*hi
                mma_k8(D + 60 + 4 * j, A8[6], A8[7], B.x);   // m1 lo*hi
                mma_k8(D + 4 * j,      A8[0], A8[1], B.y);   // m0 hi*lo
                mma_k8(D + 60 + 4 * j, A8[4], A8[5], B.y);   // m1 hi*lo
            }
        }

        // ---- all slab reads done: prefetch x(t+1) ----
        if (t < NT - 1) {
#pragma unroll
            for (int k = 0; k < 9; k++) {
                int i = lane + 32 * k;
                int rr = i / 9, q = i - rr * 9;
                CP16(slab_u + (rr * PITCH + 4 * q) * 4,
                     x + (size_t)(wB + rr) * (NT * NIn) + (t + 1) * NIn + 4 * q);
            }
            CP_COMMIT();
        }

        // ---- epilogue: 2 cells per lane per ntile; 2 shfls per (j,m) ----
#pragma unroll
        for (int j = 0; j < NTILE; j++) {
#pragma unroll
            for (int m = 0; m < 2; m++) {
                float* Dm = D + 60 * m + 4 * j;
                float d0 = Dm[0], d1 = Dm[1], d2 = Dm[2], d3 = Dm[3];
                // even lane sends d2/d3 (odd needs them), odd sends d0/d1
                float s0 = __shfl_xor_sync(0xffffffffu, ev ? d2 : d0, 1);
                float s1 = __shfl_xor_sync(0xffffffffu, ev ? d3 : d1, 1);
                float gi = ev ? d0 : s0;
                float gf = ev ? d1 : s1;
                float gg = ev ? s0 : d2;
                float go = ev ? s1 : d3;
                float it = sigmoid_f(gi), ft = sigmoid_f(gf);
                float gt = tanh_f(gg),    ot = sigmoid_f(go);
                float* cr = m ? c1 : c0;
                float cn = fmaf(ft, cr[j], it * gt);
                cr[j] = cn;
                slab[(rowp + 16 * m) * PITCH + 36 + (2 * j + hsel)] = ot * tanh_f(cn);
            }
        }
        __syncwarp();

        // ---- out write: 32 rows x 30 from slab h cols ----
#pragma unroll
        for (int k = 0; k < 30; k++) {
            int i = lane + 32 * k;                  // < 960
            int rr = i / 30, cc = i - rr * 30;
            out[(size_t)(wB + rr) * (NT * NH) + t * NH + cc] =
                slab[rr * PITCH + 36 + cc];
        }
        __syncwarp();   // h reads done before next t's A-frag build
    }

    // ---- final states ----
    float* hN = out + (size_t)NB * NT * NH;
    float* cN = hN + (size_t)NB * NH;
#pragma unroll
    for (int k = 0; k < 30; k++) {
        int i = lane + 32 * k;
        int rr = i / 30, cc = i - rr * 30;
        hN[(size_t)(wB + rr) * NH + cc] = slab[rr * PITCH + 36 + cc];
    }
    __syncwarp();
#pragma unroll
    for (int j = 0; j < NTILE; j++) {
        slab[rowp * PITCH + 36 + (2 * j + hsel)]        = c0[j];
        slab[(rowp + 16) * PITCH + 36 + (2 * j + hsel)] = c1[j];
    }
    __syncwarp();
#pragma unroll
    for (int k = 0; k < 30; k++) {
        int i = lane + 32 * k;
        int rr = i / 30, cc = i - rr * 30;
        cN[(size_t)(wB + rr) * NH + cc] = slab[rr * PITCH + 36 + cc];
    }
}

extern "C" void kernel_launch(void* const* d_in, const int* in_sizes, int n_in,
                              void* d_out, int out_size) {
    const float* x    = (const float*)d_in[0];
    const float* W_ih = (const float*)d_in[1];
    const float* W_hh = (const float*)d_in[2];
    const float* b_ih = (const float*)d_in[3];
    const float* b_hh = (const float*)d_in[4];
    float* out = (float*)d_out;

    cudaFuncSetAttribute(lstm_hmma_f16,
                         cudaFuncAttributeMaxDynamicSharedMemorySize, SMEM_BYTES);
    lstm_hmma_f16<<<GRID, BLOCK, SMEM_BYTES>>>(x, W_ih, W_hh, b_ih, b_hh, out);
}

// round 13
// speedup vs baseline: 2.2872x; 1.3167x over previous
#include <cuda_runtime.h>
#include <cstdint>

typedef unsigned int u32;

// LSTM B=65536, T=20, I=36, H=30. Gate order i,f,g,o.
// Output: out[B,T,H] ++ h_n[1,B,H] ++ c_n[1,B,H], fp32.
//
// R12 skeleton (M=32/warp, D[120] live, ch-outer j-inner, 2 CTAs/SM) with:
//  - ALL chunks fp16 2-pass (AhiBhi + AloBhi), B hi-only (incl. k8 + bias)
//  - activations via tanh.approx.f32 (MUFU.TANH): 1 MUFU per activation

#define NB   65536
#define NT   20
#define NIn  36
#define NH   30

#define BLOCK 128                 // 4 warps, 128 batches per CTA
#define GRID  (NB / 128)          // 512

#define PITCH 72                  // x 0..35 | h 36..65 | bias(66)=1 | zeros
#define SLAB_FLOATS (32 * PITCH)  // 2304
#define SLAB_BYTES  (SLAB_FLOATS * 4)   // 9216
#define NTILE  15                 // N = 120 = 15 x 8, n = hh*4 + gate

// smem layout (bytes)
#define OFF_BF16 0                         // fp16 hi-only k16: 4ch*15j*32*uint2 = 15360
#define OFF_B8   15360                     // k8 fp16 hi-only: 15j*32*u32 = 1920
#define OFF_SLAB 17280
#define SMEM_BYTES (OFF_SLAB + 4 * SLAB_BYTES)   // 54144

// ---- fp16 helpers ----
__device__ __forceinline__ u32 f16x2_rn(float even, float odd) {
    u32 d;
    asm("cvt.rn.f16x2.f32 %0, %1, %2;" : "=r"(d) : "f"(odd), "f"(even));
    return d;
}
__device__ __forceinline__ void mk_ahl_f16(float2 f, u32& hi, u32& lo) {
    u32 h = f16x2_rn(f.x, f.y);
    float b0, b1;
    asm("{.reg .b16 l16, h16; mov.b32 {l16, h16}, %2;"
        " cvt.f32.f16 %0, l16; cvt.f32.f16 %1, h16;}"
        : "=f"(b0), "=f"(b1) : "r"(h));
    lo = f16x2_rn(f.x - b0, f.y - b1);
    hi = h;
}

// ---- MMA wrappers ----
__device__ __forceinline__ void mma_f16(float* d, u32 a0, u32 a1, u32 a2, u32 a3,
                                        u32 b0, u32 b1) {
    asm volatile(
        "mma.sync.aligned.m16n8k16.row.col.f32.f16.f16.f32 "
        "{%0,%1,%2,%3}, {%4,%5,%6,%7}, {%8,%9}, {%0,%1,%2,%3};"
        : "+f"(d[0]), "+f"(d[1]), "+f"(d[2]), "+f"(d[3])
        : "r"(a0), "r"(a1), "r"(a2), "r"(a3), "r"(b0), "r"(b1));
}
__device__ __forceinline__ void mma_k8_f16(float* d, u32 a0, u32 a1, u32 b0) {
    asm volatile(
        "mma.sync.aligned.m16n8k8.row.col.f32.f16.f16.f32 "
        "{%0,%1,%2,%3}, {%4,%5}, {%6}, {%0,%1,%2,%3};"
        : "+f"(d[0]), "+f"(d[1]), "+f"(d[2]), "+f"(d[3])
        : "r"(a0), "r"(a1), "r"(b0));
}

// ---- activations: MUFU.TANH based ----
__device__ __forceinline__ float tanh_ap(float v) {
    float y;
    asm("tanh.approx.f32 %0, %1;" : "=f"(y) : "f"(v));
    return y;
}
__device__ __forceinline__ float sigmoid_f(float v) {
    return fmaf(tanh_ap(0.5f * v), 0.5f, 0.5f);
}

__device__ __forceinline__ u32 s2u(const void* p) {
    u32 a;
    asm("{ .reg .u64 t; cvta.to.shared.u64 t, %1; cvt.u32.u64 %0, t; }"
        : "=r"(a) : "l"(p));
    return a;
}
#define CP16(dst, src) \
    asm volatile("cp.async.cg.shared.global [%0], [%1], 16;" :: "r"(dst), "l"(src))
#define CP_COMMIT() asm volatile("cp.async.commit_group;" ::: "memory")
#define CP_WAIT0()  asm volatile("cp.async.wait_group 0;" ::: "memory")

// concatenated weights: row n (gate-interleaved), col k in [0,72)
__device__ __forceinline__ float wcat(int n, int k,
                                      const float* W_ih, const float* W_hh,
                                      const float* b_ih, const float* b_hh) {
    int g = n & 3, hh = n >> 2;
    int row = g * NH + hh;
    if (k < 36) return W_ih[row * NIn + k];
    if (k < 66) return W_hh[row * NH + (k - 36)];
    if (k == 66) return b_ih[row] + b_hh[row];
    return 0.0f;
}

__global__ void __launch_bounds__(BLOCK, 2)
lstm_hmma_t13(const float* __restrict__ x,
              const float* __restrict__ W_ih,
              const float* __restrict__ W_hh,
              const float* __restrict__ b_ih,
              const float* __restrict__ b_hh,
              float* __restrict__ out) {
    extern __shared__ __align__(16) char smraw[];
    uint2* BsF = reinterpret_cast<uint2*>(smraw + OFF_BF16);   // k16 fp16 hi-only
    u32*   Bs8 = reinterpret_cast<u32*>(smraw + OFF_B8);       // k8 fp16 hi-only
    float* slab = reinterpret_cast<float*>(smraw + OFF_SLAB) + (threadIdx.x >> 5) * SLAB_FLOATS;

    const int tid  = threadIdx.x;
    const int lane = tid & 31;
    const int wB   = blockIdx.x * 128 + (tid >> 5) * 32;   // warp's first batch
    const u32 slab_u = s2u(slab);

    // ---- B tables (one-time) ----
    // fp16 hi-only k16 chunks: k = 0..63
    for (int idx = tid; idx < 4 * NTILE * 32; idx += BLOCK) {
        int ch  = idx / (NTILE * 32);
        int rem = idx - ch * NTILE * 32;
        int j   = rem >> 5, ln = rem & 31;
        int n   = j * 8 + (ln >> 2);
        int kb  = 16 * ch + 2 * (ln & 3);
        uint2 e;
        e.x = f16x2_rn(wcat(n, kb,     W_ih, W_hh, b_ih, b_hh),
                       wcat(n, kb + 1, W_ih, W_hh, b_ih, b_hh));
        e.y = f16x2_rn(wcat(n, kb + 8, W_ih, W_hh, b_ih, b_hh),
                       wcat(n, kb + 9, W_ih, W_hh, b_ih, b_hh));
        BsF[idx] = e;
    }
    // k8 chunk: k = 64..71 (h28, h29, bias col 66, zeros), fp16 hi-only
    for (int idx = tid; idx < NTILE * 32; idx += BLOCK) {
        int j = idx >> 5, ln = idx & 31;
        int n = j * 8 + (ln >> 2);
        int kb = 64 + 2 * (ln & 3);
        Bs8[idx] = f16x2_rn(wcat(n, kb,     W_ih, W_hh, b_ih, b_hh),
                            wcat(n, kb + 1, W_ih, W_hh, b_ih, b_hh));
    }

    // ---- per-warp slab init: zeros, bias column 66 = 1 ----
#pragma unroll
    for (int i = lane; i < SLAB_FLOATS / 4; i += 32)
        *reinterpret_cast<float4*>(slab + 4 * i) = make_float4(0, 0, 0, 0);
    __syncwarp();
    slab[lane * PITCH + 66] = 1.0f;     // one row per lane
    __syncthreads();

    // ---- prefetch x(t=0) via cp.async (cols 0..35 exactly) ----
#pragma unroll
    for (int k = 0; k < 9; k++) {
        int i = lane + 32 * k;          // 32 rows * 9 quads
        int rr = i / 9, q = i - rr * 9;
        CP16(slab_u + (rr * PITCH + 4 * q) * 4,
             x + (size_t)(wB + rr) * (NT * NIn) + 4 * q);
    }
    CP_COMMIT();

    const int r    = lane >> 2;               // frag row 0..7
    const bool ev  = (lane & 1) == 0;
    const int rowp = r + (ev ? 0 : 8);        // m0 cell row; m1 = rowp+16
    const int hsel = (lane >> 1) & 1;         // hh = 2j + hsel
    const int kofs = 2 * (lane & 3);

    float c0[NTILE], c1[NTILE];
#pragma unroll
    for (int j = 0; j < NTILE; j++) { c0[j] = 0.0f; c1[j] = 0.0f; }

    for (int t = 0; t < NT; t++) {
        CP_WAIT0();
        __syncwarp();                         // x(t) and h(t-1) visible

        float D[8 * NTILE];                   // m0: 0..59, m1: 60..119
#pragma unroll
        for (int i = 0; i < 8 * NTILE; i++) D[i] = 0.0f;

        // ---- fp16 2-pass k16 chunks: k 0..63 ----
#pragma unroll
        for (int ch = 0; ch < 4; ch++) {
            int kb = 16 * ch + kofs;
            u32 A[16];
            mk_ahl_f16(*reinterpret_cast<const float2*>(slab + r * PITCH + kb),            A[0], A[4]);
            mk_ahl_f16(*reinterpret_cast<const float2*>(slab + (r + 8) * PITCH + kb),      A[1], A[5]);
            mk_ahl_f16(*reinterpret_cast<const float2*>(slab + r * PITCH + kb + 8),        A[2], A[6]);
            mk_ahl_f16(*reinterpret_cast<const float2*>(slab + (r + 8) * PITCH + kb + 8),  A[3], A[7]);
            mk_ahl_f16(*reinterpret_cast<const float2*>(slab + (r + 16) * PITCH + kb),     A[8], A[12]);
            mk_ahl_f16(*reinterpret_cast<const float2*>(slab + (r + 24) * PITCH + kb),     A[9], A[13]);
            mk_ahl_f16(*reinterpret_cast<const float2*>(slab + (r + 16) * PITCH + kb + 8), A[10], A[14]);
            mk_ahl_f16(*reinterpret_cast<const float2*>(slab + (r + 24) * PITCH + kb + 8), A[11], A[15]);
#pragma unroll
            for (int j = 0; j < NTILE; j++) {
                uint2 B = BsF[(ch * NTILE + j) * 32 + lane];
                mma_f16(D + 4 * j,      A[0], A[1], A[2],  A[3],  B.x, B.y);  // m0 hi
                mma_f16(D + 60 + 4 * j, A[8], A[9], A[10], A[11], B.x, B.y);  // m1 hi
                mma_f16(D + 4 * j,      A[4], A[5], A[6],  A[7],  B.x, B.y);  // m0 lo
                mma_f16(D + 60 + 4 * j, A[12],A[13],A[14], A[15], B.x, B.y);  // m1 lo
            }
        }

        // ---- k8 chunk: k 64..71 (h tail + bias), fp16 2-pass ----
        {
            int kb = 64 + kofs;
            u32 A8[8];
            mk_ahl_f16(*reinterpret_cast<const float2*>(slab + r * PITCH + kb),        A8[0], A8[2]);
            mk_ahl_f16(*reinterpret_cast<const float2*>(slab + (r + 8) * PITCH + kb),  A8[1], A8[3]);
            mk_ahl_f16(*reinterpret_cast<const float2*>(slab + (r + 16) * PITCH + kb), A8[4], A8[6]);
            mk_ahl_f16(*reinterpret_cast<const float2*>(slab + (r + 24) * PITCH + kb), A8[5], A8[7]);
#pragma unroll
            for (int j = 0; j < NTILE; j++) {
                u32 B = Bs8[j * 32 + lane];
                mma_k8_f16(D + 4 * j,      A8[0], A8[1], B);   // m0 hi
                mma_k8_f16(D + 60 + 4 * j, A8[4], A8[5], B);   // m1 hi
                mma_k8_f16(D + 4 * j,      A8[2], A8[3], B);   // m0 lo
                mma_k8_f16(D + 60 + 4 * j, A8[6], A8[7], B);   // m1 lo
            }
        }

        // ---- all slab reads done: prefetch x(t+1) ----
        if (t < NT - 1) {
#pragma unroll
            for (int k = 0; k < 9; k++) {
                int i = lane + 32 * k;
                int rr = i / 9, q = i - rr * 9;
                CP16(slab_u + (rr * PITCH + 4 * q) * 4,
                     x + (size_t)(wB + rr) * (NT * NIn) + (t + 1) * NIn + 4 * q);
            }
            CP_COMMIT();
        }

        // ---- epilogue: 2 cells per lane per ntile; 2 shfls per (j,m) ----
#pragma unroll
        for (int j = 0; j < NTILE; j++) {
#pragma unroll
            for (int m = 0; m < 2; m++) {
                float* Dm = D + 60 * m + 4 * j;
                float d0 = Dm[0], d1 = Dm[1], d2 = Dm[2], d3 = Dm[3];
                // even lane sends d2/d3 (odd needs them), odd sends d0/d1
                float s0 = __shfl_xor_sync(0xffffffffu, ev ? d2 : d0, 1);
                float s1 = __shfl_xor_sync(0xffffffffu, ev ? d3 : d1, 1);
                float gi = ev ? d0 : s0;
                float gf = ev ? d1 : s1;
                float gg = ev ? s0 : d2;
                float go = ev ? s1 : d3;
                float it = sigmoid_f(gi), ft = sigmoid_f(gf);
                float gt = tanh_ap(gg),   ot = sigmoid_f(go);
                float* cr = m ? c1 : c0;
                float cn = fmaf(ft, cr[j], it * gt);
                cr[j] = cn;
                slab[(rowp + 16 * m) * PITCH + 36 + (2 * j + hsel)] = ot * tanh_ap(cn);
            }
        }
        __syncwarp();

        // ---- out write: 32 rows x 30 from slab h cols ----
#pragma unroll
        for (int k = 0; k < 30; k++) {
            int i = lane + 32 * k;                  // < 960
            int rr = i / 30, cc = i - rr * 30;
            out[(size_t)(wB + rr) * (NT * NH) + t * NH + cc] =
                slab[rr * PITCH + 36 + cc];
        }
        __syncwarp();   // h reads done before next t's A-frag build
    }

    // ---- final states ----
    float* hN = out + (size_t)NB * NT * NH;
    float* cN = hN + (size_t)NB * NH;
#pragma unroll
    for (int k = 0; k < 30; k++) {
        int i = lane + 32 * k;
        int rr = i / 30, cc = i - rr * 30;
        hN[(size_t)(wB + rr) * NH + cc] = slab[rr * PITCH + 36 + cc];
    }
    __syncwarp();
#pragma unroll
    for (int j = 0; j < NTILE; j++) {
        slab[rowp * PITCH + 36 + (2 * j + hsel)]        = c0[j];
        slab[(rowp + 16) * PITCH + 36 + (2 * j + hsel)] = c1[j];
    }
    __syncwarp();
#pragma unroll
    for (int k = 0; k < 30; k++) {
        int i = lane + 32 * k;
        int rr = i / 30, cc = i - rr * 30;
        cN[(size_t)(wB + rr) * NH + cc] = slab[rr * PITCH + 36 + cc];
    }
}

extern "C" void kernel_launch(void* const* d_in, const int* in_sizes, int n_in,
                              void* d_out, int out_size) {
    const float* x    = (const float*)d_in[0];
    const float* W_ih = (const float*)d_in[1];
    const float* W_hh = (const float*)d_in[2];
    const float* b_ih = (const float*)d_in[3];
    const float* b_hh = (const float*)d_in[4];
    float* out = (float*)d_out;

    cudaFuncSetAttribute(lstm_hmma_t13,
                         cudaFuncAttributeMaxDynamicSharedMemorySize, SMEM_BYTES);
    lstm_hmma_t13<<<GRID, BLOCK, SMEM_BYTES>>>(x, W_ih, W_hh, b_ih, b_hh, out);
}